// round 11
// baseline (speedup 1.0000x reference)
#include <cuda_runtime.h>

// H=1080, W=1920 (n_pix = 2,073,600, /4 ok), S=2000, C=8.
// Output (float32): [1,1,H,W] preseg then [7,4,H,W] attmaps, flattened.
//
// Compact smem table, 20 floats (80 B) per superpixel:
//   [0..3]   k[1..4]
//   [4..7]   k[5..7], km1        (km1 = max over all 8 knn)
//   [8..11]  c[1..4]
//   [12..15] c[5..7], cm1
//   [16..19] km2, cm2, as_float(ka | ca<<16), (float)pred
// Leave-one-out max reconstructed per pixel: loo[j] = (j==argmax) ? m2 : m1.

#define NJ   7
#define NCLS 8
#define ROWF 20

__device__ __forceinline__ float getc(const float4 v, int i) {
    return i == 0 ? v.x : i == 1 ? v.y : i == 2 ? v.z : v.w;
}

__global__ __launch_bounds__(1024, 1)
void fused_scatter_kernel(const int* __restrict__ spx,
                          const int* __restrict__ pred,
                          const float* __restrict__ knn,
                          const float* __restrict__ cent,
                          float* __restrict__ out,
                          int S, int n4, int n_pix)
{
    extern __shared__ float att[];
    const float NEG_INF = -__int_as_float(0x7f800000);

    // ---- Phase 1: build compact table in smem ----
    for (int s = threadIdx.x; s < S; s += blockDim.x) {
        float4 k0 = __ldg((const float4*)knn  + (size_t)s * 2);
        float4 k1 = __ldg((const float4*)knn  + (size_t)s * 2 + 1);
        float4 c0 = __ldg((const float4*)cent + (size_t)s * 2);
        float4 c1 = __ldg((const float4*)cent + (size_t)s * 2 + 1);
        float k[NCLS] = {k0.x, k0.y, k0.z, k0.w, k1.x, k1.y, k1.z, k1.w};
        float c[NCLS] = {c0.x, c0.y, c0.z, c0.w, c1.x, c1.y, c1.z, c1.w};

        float km1 = k[0], km2 = NEG_INF; int ka = 0;
#pragma unroll
        for (int j = 1; j < NCLS; j++) {
            if (k[j] > km1)      { km2 = km1; km1 = k[j]; ka = j; }
            else if (k[j] > km2) { km2 = k[j]; }
        }
        float cm1 = c[0], cm2 = NEG_INF; int ca = 0;
#pragma unroll
        for (int j = 1; j < NCLS; j++) {
            if (c[j] > cm1)      { cm2 = cm1; cm1 = c[j]; ca = j; }
            else if (c[j] > cm2) { cm2 = c[j]; }
        }

        float4* row = (float4*)(att + (size_t)s * ROWF);
        row[0] = make_float4(k[1], k[2], k[3], k[4]);
        row[1] = make_float4(k[5], k[6], k[7], km1);
        row[2] = make_float4(c[1], c[2], c[3], c[4]);
        row[3] = make_float4(c[5], c[6], c[7], cm1);
        row[4] = make_float4(km2, cm2,
                             __int_as_float(ka | (ca << 16)),
                             (float)__ldg(pred + s));
    }
    __syncthreads();

    // ---- Phase 2: stream pixels, 4/thread, prefetched labels ----
    int stride = gridDim.x * blockDim.x;
    int t = blockIdx.x * blockDim.x + threadIdx.x;
    if (t >= n4) return;

    int4 lab = __ldcs((const int4*)spx + t);
    for (; t < n4; t += stride) {
        int tn = t + stride;
        int4 labn = (tn < n4) ? __ldcs((const int4*)spx + tn) : lab;

        int o0 = (lab.x - 1) * ROWF;
        int o1 = (lab.y - 1) * ROWF;
        int o2 = (lab.z - 1) * ROWF;
        int o3 = (lab.w - 1) * ROWF;

        float4 m0 = *(const float4*)(att + o0 + 16);
        float4 m1 = *(const float4*)(att + o1 + 16);
        float4 m2 = *(const float4*)(att + o2 + 16);
        float4 m3 = *(const float4*)(att + o3 + 16);

        size_t p = (size_t)t * 4;

        // preseg plane
        __stcs((float4*)(out + p), make_float4(m0.w, m1.w, m2.w, m3.w));

        // ---- knn planes (4*jj+0, 4*jj+1) ----
        {
            float4 a0 = *(const float4*)(att + o0);
            float4 a1 = *(const float4*)(att + o0 + 4);
            float4 b0 = *(const float4*)(att + o1);
            float4 b1 = *(const float4*)(att + o1 + 4);
            float4 c0 = *(const float4*)(att + o2);
            float4 c1 = *(const float4*)(att + o2 + 4);
            float4 d0 = *(const float4*)(att + o3);
            float4 d1 = *(const float4*)(att + o3 + 4);
            int ka0 = __float_as_int(m0.z) & 0xffff;
            int ka1 = __float_as_int(m1.z) & 0xffff;
            int ka2 = __float_as_int(m2.z) & 0xffff;
            int ka3 = __float_as_int(m3.z) & 0xffff;

            float* q = out + (size_t)n_pix + p;
#pragma unroll
            for (int jj = 0; jj < NJ; jj++) {
                float v0 = jj < 4 ? getc(a0, jj) : getc(a1, jj - 4);
                float v1 = jj < 4 ? getc(b0, jj) : getc(b1, jj - 4);
                float v2 = jj < 4 ? getc(c0, jj) : getc(c1, jj - 4);
                float v3 = jj < 4 ? getc(d0, jj) : getc(d1, jj - 4);
                float l0 = (jj + 1 == ka0) ? m0.x : a1.w;
                float l1 = (jj + 1 == ka1) ? m1.x : b1.w;
                float l2 = (jj + 1 == ka2) ? m2.x : c1.w;
                float l3 = (jj + 1 == ka3) ? m3.x : d1.w;
                __stcs((float4*)q,                   make_float4(v0, v1, v2, v3));
                __stcs((float4*)(q + (size_t)n_pix), make_float4(l0, l1, l2, l3));
                q += (size_t)4 * n_pix;
            }
        }

        // ---- cent planes (4*jj+2, 4*jj+3) ----
        {
            float4 a0 = *(const float4*)(att + o0 + 8);
            float4 a1 = *(const float4*)(att + o0 + 12);
            float4 b0 = *(const float4*)(att + o1 + 8);
            float4 b1 = *(const float4*)(att + o1 + 12);
            float4 c0 = *(const float4*)(att + o2 + 8);
            float4 c1 = *(const float4*)(att + o2 + 12);
            float4 d0 = *(const float4*)(att + o3 + 8);
            float4 d1 = *(const float4*)(att + o3 + 12);
            int ca0 = __float_as_int(m0.z) >> 16;
            int ca1 = __float_as_int(m1.z) >> 16;
            int ca2 = __float_as_int(m2.z) >> 16;
            int ca3 = __float_as_int(m3.z) >> 16;

            float* q = out + (size_t)n_pix + p + (size_t)2 * n_pix;
#pragma unroll
            for (int jj = 0; jj < NJ; jj++) {
                float v0 = jj < 4 ? getc(a0, jj) : getc(a1, jj - 4);
                float v1 = jj < 4 ? getc(b0, jj) : getc(b1, jj - 4);
                float v2 = jj < 4 ? getc(c0, jj) : getc(c1, jj - 4);
                float v3 = jj < 4 ? getc(d0, jj) : getc(d1, jj - 4);
                float l0 = (jj + 1 == ca0) ? m0.y : a1.w;
                float l1 = (jj + 1 == ca1) ? m1.y : b1.w;
                float l2 = (jj + 1 == ca2) ? m2.y : c1.w;
                float l3 = (jj + 1 == ca3) ? m3.y : d1.w;
                __stcs((float4*)q,                   make_float4(v0, v1, v2, v3));
                __stcs((float4*)(q + (size_t)n_pix), make_float4(l0, l1, l2, l3));
                q += (size_t)4 * n_pix;
            }
        }

        lab = labn;
    }
}

extern "C" void kernel_launch(void* const* d_in, const int* in_sizes, int n_in,
                              void* d_out, int out_size) {
    const int*   spx  = (const int*)d_in[0];
    const int*   pred = (const int*)d_in[1];
    const float* knn  = (const float*)d_in[2];
    const float* cent = (const float*)d_in[3];
    float* out = (float*)d_out;

    int n_pix = in_sizes[0];   // 2,073,600
    int S     = in_sizes[1];   // 2000
    int n4    = n_pix / 4;

    size_t smem_bytes = (size_t)S * ROWF * sizeof(float);  // 160,000 B

    cudaFuncSetAttribute(fused_scatter_kernel,
                         cudaFuncAttributeMaxDynamicSharedMemorySize,
                         (int)smem_bytes);

    int nsm = 148;
    cudaDeviceGetAttribute(&nsm, cudaDevAttrMultiProcessorCount, 0);

    fused_scatter_kernel<<<nsm, 1024, smem_bytes>>>(
        spx, pred, knn, cent, out, S, n4, n_pix);
}

// round 12
// speedup vs baseline: 1.0249x; 1.0249x over previous
#include <cuda_runtime.h>

// H=1080, W=1920 (n_pix = 2,073,600, /4 ok), S=2000, C=8.
// Output (float32): [1,1,H,W] preseg then [7,4,H,W] attmaps, flattened.
//
// R9 design (measured best) + contiguous per-CTA chunks for DRAM page locality.
// Full precomputed table in smem: S x 28 floats (att) + S floats (pred).

#define NCLS 8
#define NJ   7

__global__ __launch_bounds__(1024, 1)
void fused_scatter_kernel(const int* __restrict__ spx,
                          const int* __restrict__ pred,
                          const float* __restrict__ knn,
                          const float* __restrict__ cent,
                          float* __restrict__ out,
                          int S, int n4, int n_pix)
{
    extern __shared__ float smem[];
    float* att = smem;                       // S rows x 28 floats (112 B)
    float* prd = smem + (size_t)S * 28;      // S floats

    const float NEG_INF = -__int_as_float(0x7f800000);

    // ---- Phase 1: build precomputed table in smem ----
    for (int s = threadIdx.x; s < S; s += blockDim.x) {
        float4 k0 = __ldg((const float4*)knn  + (size_t)s * 2);
        float4 k1 = __ldg((const float4*)knn  + (size_t)s * 2 + 1);
        float4 c0 = __ldg((const float4*)cent + (size_t)s * 2);
        float4 c1 = __ldg((const float4*)cent + (size_t)s * 2 + 1);
        float k[NCLS] = {k0.x, k0.y, k0.z, k0.w, k1.x, k1.y, k1.z, k1.w};
        float c[NCLS] = {c0.x, c0.y, c0.z, c0.w, c1.x, c1.y, c1.z, c1.w};

        float km1 = k[0], km2 = NEG_INF; int ka = 0;
#pragma unroll
        for (int j = 1; j < NCLS; j++) {
            if (k[j] > km1)      { km2 = km1; km1 = k[j]; ka = j; }
            else if (k[j] > km2) { km2 = k[j]; }
        }
        float cm1 = c[0], cm2 = NEG_INF; int ca = 0;
#pragma unroll
        for (int j = 1; j < NCLS; j++) {
            if (c[j] > cm1)      { cm2 = cm1; cm1 = c[j]; ca = j; }
            else if (c[j] > cm2) { cm2 = c[j]; }
        }

        float4* row = (float4*)(att + (size_t)s * 28);
#pragma unroll
        for (int jj = 0; jj < NJ; jj++) {
            int j = jj + 1;
            row[jj] = make_float4(k[j], (j == ka) ? km2 : km1,
                                  c[j], (j == ca) ? cm2 : cm1);
        }
        prd[s] = (float)__ldg(pred + s);
    }
    __syncthreads();

    // ---- Phase 2: contiguous per-CTA chunk, 4 pixels/thread ----
    int chunk = (n4 + gridDim.x - 1) / gridDim.x;
    int begin = blockIdx.x * chunk;
    int end   = begin + chunk;
    if (end > n4) end = n4;

    int t = begin + threadIdx.x;
    if (t >= end) return;

    int4 lab = __ldcs((const int4*)spx + t);
    for (; t < end; t += blockDim.x) {
        int tn = t + blockDim.x;
        int4 labn = (tn < end) ? __ldcs((const int4*)spx + tn) : lab;

        const float4* r0 = (const float4*)(att + (size_t)(lab.x - 1) * 28);
        const float4* r1 = (const float4*)(att + (size_t)(lab.y - 1) * 28);
        const float4* r2 = (const float4*)(att + (size_t)(lab.z - 1) * 28);
        const float4* r3 = (const float4*)(att + (size_t)(lab.w - 1) * 28);

        size_t p = (size_t)t * 4;

        // preseg plane
        __stcs((float4*)(out + p),
               make_float4(prd[lab.x - 1], prd[lab.y - 1],
                           prd[lab.z - 1], prd[lab.w - 1]));

        // 28 attmap planes
        float* q = out + (size_t)n_pix + p;
#pragma unroll
        for (int g = 0; g < NJ; g++) {
            float4 a  = r0[g];
            float4 b  = r1[g];
            float4 cc = r2[g];
            float4 d  = r3[g];
            __stcs((float4*)q,                       make_float4(a.x, b.x, cc.x, d.x));
            __stcs((float4*)(q + (size_t)n_pix),     make_float4(a.y, b.y, cc.y, d.y));
            __stcs((float4*)(q + (size_t)2 * n_pix), make_float4(a.z, b.z, cc.z, d.z));
            __stcs((float4*)(q + (size_t)3 * n_pix), make_float4(a.w, b.w, cc.w, d.w));
            q += (size_t)4 * n_pix;
        }

        lab = labn;
    }
}

extern "C" void kernel_launch(void* const* d_in, const int* in_sizes, int n_in,
                              void* d_out, int out_size) {
    const int*   spx  = (const int*)d_in[0];
    const int*   pred = (const int*)d_in[1];
    const float* knn  = (const float*)d_in[2];
    const float* cent = (const float*)d_in[3];
    float* out = (float*)d_out;

    int n_pix = in_sizes[0];   // 2,073,600
    int S     = in_sizes[1];   // 2000
    int n4    = n_pix / 4;

    size_t smem_bytes = (size_t)S * 29 * sizeof(float);  // 232,000 B

    cudaFuncSetAttribute(fused_scatter_kernel,
                         cudaFuncAttributeMaxDynamicSharedMemorySize,
                         (int)smem_bytes);

    int nsm = 148;
    cudaDeviceGetAttribute(&nsm, cudaDevAttrMultiProcessorCount, 0);

    fused_scatter_kernel<<<nsm, 1024, smem_bytes>>>(
        spx, pred, knn, cent, out, S, n4, n_pix);
}

// round 13
// speedup vs baseline: 1.0298x; 1.0048x over previous
#include <cuda_runtime.h>

// H=1080, W=1920 (n_pix = 2,073,600, /4 ok), S=2000, C=8.
// Output (float32): [1,1,H,W] preseg then [7,4,H,W] attmaps, flattened.
//
// R9 design (measured best) + contiguous per-CTA chunks for DRAM page locality.
// Full precomputed table in smem: S x 28 floats (att) + S floats (pred).

#define NCLS 8
#define NJ   7

__global__ __launch_bounds__(1024, 1)
void fused_scatter_kernel(const int* __restrict__ spx,
                          const int* __restrict__ pred,
                          const float* __restrict__ knn,
                          const float* __restrict__ cent,
                          float* __restrict__ out,
                          int S, int n4, int n_pix)
{
    extern __shared__ float smem[];
    float* att = smem;                       // S rows x 28 floats (112 B)
    float* prd = smem + (size_t)S * 28;      // S floats

    const float NEG_INF = -__int_as_float(0x7f800000);

    // ---- Phase 1: build precomputed table in smem ----
    for (int s = threadIdx.x; s < S; s += blockDim.x) {
        float4 k0 = __ldg((const float4*)knn  + (size_t)s * 2);
        float4 k1 = __ldg((const float4*)knn  + (size_t)s * 2 + 1);
        float4 c0 = __ldg((const float4*)cent + (size_t)s * 2);
        float4 c1 = __ldg((const float4*)cent + (size_t)s * 2 + 1);
        float k[NCLS] = {k0.x, k0.y, k0.z, k0.w, k1.x, k1.y, k1.z, k1.w};
        float c[NCLS] = {c0.x, c0.y, c0.z, c0.w, c1.x, c1.y, c1.z, c1.w};

        float km1 = k[0], km2 = NEG_INF; int ka = 0;
#pragma unroll
        for (int j = 1; j < NCLS; j++) {
            if (k[j] > km1)      { km2 = km1; km1 = k[j]; ka = j; }
            else if (k[j] > km2) { km2 = k[j]; }
        }
        float cm1 = c[0], cm2 = NEG_INF; int ca = 0;
#pragma unroll
        for (int j = 1; j < NCLS; j++) {
            if (c[j] > cm1)      { cm2 = cm1; cm1 = c[j]; ca = j; }
            else if (c[j] > cm2) { cm2 = c[j]; }
        }

        float4* row = (float4*)(att + (size_t)s * 28);
#pragma unroll
        for (int jj = 0; jj < NJ; jj++) {
            int j = jj + 1;
            row[jj] = make_float4(k[j], (j == ka) ? km2 : km1,
                                  c[j], (j == ca) ? cm2 : cm1);
        }
        prd[s] = (float)__ldg(pred + s);
    }
    __syncthreads();

    // ---- Phase 2: contiguous per-CTA chunk, 4 pixels/thread ----
    int chunk = (n4 + gridDim.x - 1) / gridDim.x;
    int begin = blockIdx.x * chunk;
    int end   = begin + chunk;
    if (end > n4) end = n4;

    int t = begin + threadIdx.x;
    if (t >= end) return;

    int4 lab = __ldcs((const int4*)spx + t);
    for (; t < end; t += blockDim.x) {
        int tn = t + blockDim.x;
        int4 labn = (tn < end) ? __ldcs((const int4*)spx + tn) : lab;

        const float4* r0 = (const float4*)(att + (size_t)(lab.x - 1) * 28);
        const float4* r1 = (const float4*)(att + (size_t)(lab.y - 1) * 28);
        const float4* r2 = (const float4*)(att + (size_t)(lab.z - 1) * 28);
        const float4* r3 = (const float4*)(att + (size_t)(lab.w - 1) * 28);

        size_t p = (size_t)t * 4;

        // preseg plane
        __stcs((float4*)(out + p),
               make_float4(prd[lab.x - 1], prd[lab.y - 1],
                           prd[lab.z - 1], prd[lab.w - 1]));

        // 28 attmap planes
        float* q = out + (size_t)n_pix + p;
#pragma unroll
        for (int g = 0; g < NJ; g++) {
            float4 a  = r0[g];
            float4 b  = r1[g];
            float4 cc = r2[g];
            float4 d  = r3[g];
            __stcs((float4*)q,                       make_float4(a.x, b.x, cc.x, d.x));
            __stcs((float4*)(q + (size_t)n_pix),     make_float4(a.y, b.y, cc.y, d.y));
            __stcs((float4*)(q + (size_t)2 * n_pix), make_float4(a.z, b.z, cc.z, d.z));
            __stcs((float4*)(q + (size_t)3 * n_pix), make_float4(a.w, b.w, cc.w, d.w));
            q += (size_t)4 * n_pix;
        }

        lab = labn;
    }
}

extern "C" void kernel_launch(void* const* d_in, const int* in_sizes, int n_in,
                              void* d_out, int out_size) {
    const int*   spx  = (const int*)d_in[0];
    const int*   pred = (const int*)d_in[1];
    const float* knn  = (const float*)d_in[2];
    const float* cent = (const float*)d_in[3];
    float* out = (float*)d_out;

    int n_pix = in_sizes[0];   // 2,073,600
    int S     = in_sizes[1];   // 2000
    int n4    = n_pix / 4;

    size_t smem_bytes = (size_t)S * 29 * sizeof(float);  // 232,000 B

    cudaFuncSetAttribute(fused_scatter_kernel,
                         cudaFuncAttributeMaxDynamicSharedMemorySize,
                         (int)smem_bytes);

    int nsm = 148;
    cudaDeviceGetAttribute(&nsm, cudaDevAttrMultiProcessorCount, 0);

    fused_scatter_kernel<<<nsm, 1024, smem_bytes>>>(
        spx, pred, knn, cent, out, S, n4, n_pix);
}

// round 14
// speedup vs baseline: 1.0347x; 1.0048x over previous
#include <cuda_runtime.h>

// H=1080, W=1920 (n_pix = 2,073,600, /4 ok), S=2000, C=8.
// Output (float32): [1,1,H,W] preseg then [7,4,H,W] attmaps, flattened.
//
// R9 design (measured best) + contiguous per-CTA chunks for DRAM page locality.
// Full precomputed table in smem: S x 28 floats (att) + S floats (pred).

#define NCLS 8
#define NJ   7

__global__ __launch_bounds__(1024, 1)
void fused_scatter_kernel(const int* __restrict__ spx,
                          const int* __restrict__ pred,
                          const float* __restrict__ knn,
                          const float* __restrict__ cent,
                          float* __restrict__ out,
                          int S, int n4, int n_pix)
{
    extern __shared__ float smem[];
    float* att = smem;                       // S rows x 28 floats (112 B)
    float* prd = smem + (size_t)S * 28;      // S floats

    const float NEG_INF = -__int_as_float(0x7f800000);

    // ---- Phase 1: build precomputed table in smem ----
    for (int s = threadIdx.x; s < S; s += blockDim.x) {
        float4 k0 = __ldg((const float4*)knn  + (size_t)s * 2);
        float4 k1 = __ldg((const float4*)knn  + (size_t)s * 2 + 1);
        float4 c0 = __ldg((const float4*)cent + (size_t)s * 2);
        float4 c1 = __ldg((const float4*)cent + (size_t)s * 2 + 1);
        float k[NCLS] = {k0.x, k0.y, k0.z, k0.w, k1.x, k1.y, k1.z, k1.w};
        float c[NCLS] = {c0.x, c0.y, c0.z, c0.w, c1.x, c1.y, c1.z, c1.w};

        float km1 = k[0], km2 = NEG_INF; int ka = 0;
#pragma unroll
        for (int j = 1; j < NCLS; j++) {
            if (k[j] > km1)      { km2 = km1; km1 = k[j]; ka = j; }
            else if (k[j] > km2) { km2 = k[j]; }
        }
        float cm1 = c[0], cm2 = NEG_INF; int ca = 0;
#pragma unroll
        for (int j = 1; j < NCLS; j++) {
            if (c[j] > cm1)      { cm2 = cm1; cm1 = c[j]; ca = j; }
            else if (c[j] > cm2) { cm2 = c[j]; }
        }

        float4* row = (float4*)(att + (size_t)s * 28);
#pragma unroll
        for (int jj = 0; jj < NJ; jj++) {
            int j = jj + 1;
            row[jj] = make_float4(k[j], (j == ka) ? km2 : km1,
                                  c[j], (j == ca) ? cm2 : cm1);
        }
        prd[s] = (float)__ldg(pred + s);
    }
    __syncthreads();

    // ---- Phase 2: contiguous per-CTA chunk, 4 pixels/thread ----
    int chunk = (n4 + gridDim.x - 1) / gridDim.x;
    int begin = blockIdx.x * chunk;
    int end   = begin + chunk;
    if (end > n4) end = n4;

    int t = begin + threadIdx.x;
    if (t >= end) return;

    int4 lab = __ldcs((const int4*)spx + t);
    for (; t < end; t += blockDim.x) {
        int tn = t + blockDim.x;
        int4 labn = (tn < end) ? __ldcs((const int4*)spx + tn) : lab;

        const float4* r0 = (const float4*)(att + (size_t)(lab.x - 1) * 28);
        const float4* r1 = (const float4*)(att + (size_t)(lab.y - 1) * 28);
        const float4* r2 = (const float4*)(att + (size_t)(lab.z - 1) * 28);
        const float4* r3 = (const float4*)(att + (size_t)(lab.w - 1) * 28);

        size_t p = (size_t)t * 4;

        // preseg plane
        __stcs((float4*)(out + p),
               make_float4(prd[lab.x - 1], prd[lab.y - 1],
                           prd[lab.z - 1], prd[lab.w - 1]));

        // 28 attmap planes
        float* q = out + (size_t)n_pix + p;
#pragma unroll
        for (int g = 0; g < NJ; g++) {
            float4 a  = r0[g];
            float4 b  = r1[g];
            float4 cc = r2[g];
            float4 d  = r3[g];
            __stcs((float4*)q,                       make_float4(a.x, b.x, cc.x, d.x));
            __stcs((float4*)(q + (size_t)n_pix),     make_float4(a.y, b.y, cc.y, d.y));
            __stcs((float4*)(q + (size_t)2 * n_pix), make_float4(a.z, b.z, cc.z, d.z));
            __stcs((float4*)(q + (size_t)3 * n_pix), make_float4(a.w, b.w, cc.w, d.w));
            q += (size_t)4 * n_pix;
        }

        lab = labn;
    }
}

extern "C" void kernel_launch(void* const* d_in, const int* in_sizes, int n_in,
                              void* d_out, int out_size) {
    const int*   spx  = (const int*)d_in[0];
    const int*   pred = (const int*)d_in[1];
    const float* knn  = (const float*)d_in[2];
    const float* cent = (const float*)d_in[3];
    float* out = (float*)d_out;

    int n_pix = in_sizes[0];   // 2,073,600
    int S     = in_sizes[1];   // 2000
    int n4    = n_pix / 4;

    size_t smem_bytes = (size_t)S * 29 * sizeof(float);  // 232,000 B

    cudaFuncSetAttribute(fused_scatter_kernel,
                         cudaFuncAttributeMaxDynamicSharedMemorySize,
                         (int)smem_bytes);

    int nsm = 148;
    cudaDeviceGetAttribute(&nsm, cudaDevAttrMultiProcessorCount, 0);

    fused_scatter_kernel<<<nsm, 1024, smem_bytes>>>(
        spx, pred, knn, cent, out, S, n4, n_pix);
}